// round 7
// baseline (speedup 1.0000x reference)
#include <cuda_runtime.h>
#include <stdint.h>

#define COLS 16384
#define TPB  512
#define V4   (COLS / (TPB * 4))   // 8 float4 per thread
#define NW   (TPB / 32)           // 16 warps
#define CAP  2048                 // candidate list capacity
#define EQ_CAP 128

struct __align__(16) SmemT {
    union {
        unsigned           hist[NW][256];   // 16 KB : per-warp hists (level 0 only)
        unsigned long long cand[CAP];       // 16 KB : (key<<32)|idx candidates
    } u;
    unsigned tot[256];             // 1 KB : merged / refinement histogram
    int      eqIdx[EQ_CAP];
    unsigned prefix;
    int      r;
    int      eqCount;
    int      candCount;
    int      cutoff;
};

// Race-free per-warp histogram add (non-atomic; one warp owns h).
__device__ __forceinline__ void hist_add(unsigned* h, unsigned d) {
    unsigned mm = __match_any_sync(0xffffffffu, d);
    if (d < 256u) {
        unsigned leader = __ffs(mm) - 1u;
        if ((threadIdx.x & 31u) == leader) h[d] += (unsigned)__popc(mm);
    }
}

// Shared histogram add with warp aggregation (multiple warps target h).
__device__ __forceinline__ void hist_add_atomic(unsigned* h, unsigned d) {
    unsigned mm = __match_any_sync(0xffffffffu, d);
    if (d < 256u) {
        unsigned leader = __ffs(mm) - 1u;
        if ((threadIdx.x & 31u) == leader) atomicAdd(&h[d], (unsigned)__popc(mm));
    }
}

// Warp 0: find largest digit d with suffix_count(d) >= r; update prefix and r.
__device__ __forceinline__ void select_bin(SmemT* s, int shift) {
    const int lane = threadIdx.x & 31;
    const unsigned r = (unsigned)s->r;
    const unsigned base = (unsigned)lane * 8u;
    unsigned loc[8];
    unsigned sum = 0;
#pragma unroll
    for (int j = 7; j >= 0; j--) { sum += s->tot[base + j]; loc[j] = sum; }
    const unsigned lanesum = sum;
    unsigned acc = lanesum;           // inclusive suffix-scan across lanes
#pragma unroll
    for (int o = 1; o < 32; o <<= 1) {
        unsigned v = __shfl_down_sync(0xffffffffu, acc, o);
        if (lane < 32 - o) acc += v;
    }
    const unsigned above = acc - lanesum;
#pragma unroll
    for (int j = 0; j < 8; j++) {
        unsigned g     = above + loc[j];
        unsigned gnext = (j == 7) ? above : (above + loc[j+1]);
        if (g >= r && gnext < r) {
            s->prefix |= (base + (unsigned)j) << shift;
            s->r = (int)(r - gnext);
        }
    }
}

__device__ __forceinline__ void keys_of(float4 v, unsigned kk[4]) {
    kk[0] = __float_as_uint(v.x) & 0x7fffffffu;
    kk[1] = __float_as_uint(v.y) & 0x7fffffffu;
    kk[2] = __float_as_uint(v.z) & 0x7fffffffu;
    kk[3] = __float_as_uint(v.w) & 0x7fffffffu;
}

__global__ void __launch_bounds__(TPB, 4)
topk_kernel(const float* __restrict__ x, const int* __restrict__ kptr,
            float* __restrict__ out)
{
    __shared__ SmemT s;
    const int tid  = threadIdx.x;
    const int w    = tid >> 5;
    const int lane = tid & 31;
    const size_t rowoff = (size_t)blockIdx.x * COLS;
    const float4* __restrict__ xin  = reinterpret_cast<const float4*>(x + rowoff);
    float4* __restrict__       xout = reinterpret_cast<float4*>(out + rowoff);

    const int k = *kptr;
    if (k >= COLS) {
#pragma unroll
        for (int i = 0; i < V4; i++) xout[i*TPB + tid] = xin[i*TPB + tid];
        return;
    }
    if (k <= 0) {
        float4 z = make_float4(0.f, 0.f, 0.f, 0.f);
#pragma unroll
        for (int i = 0; i < V4; i++) xout[i*TPB + tid] = z;
        return;
    }

    // ---- init ----
    unsigned* hflat = &s.u.hist[0][0];
    for (int i = tid; i < NW * 256; i += TPB) hflat[i] = 0u;
    if (tid == 0) { s.prefix = 0u; s.r = k; s.eqCount = 0; s.candCount = 0; }
    __syncthreads();

    // ---- pass 1: stream row from DRAM, level-0 histogram (digit = key >> 23) ----
    unsigned* hw = s.u.hist[w];
#pragma unroll
    for (int i = 0; i < V4; i++) {
        float4 v = xin[i * TPB + tid];
        unsigned kk[4]; keys_of(v, kk);
        hist_add(hw, kk[0] >> 23);
        hist_add(hw, kk[1] >> 23);
        hist_add(hw, kk[2] >> 23);
        hist_add(hw, kk[3] >> 23);
    }
    __syncthreads();

    // ---- level 0: merge + select ----
    if (tid < 256) {
        unsigned t = 0;
#pragma unroll
        for (int ww = 0; ww < NW; ww++) t += s.u.hist[ww][tid];
        s.tot[tid] = t;
    }
    __syncthreads();
    if (tid < 32) select_bin(&s, 23);
    __syncthreads();

    // ---- pass 2 (L2 re-read): compact elements in the selected exponent bucket ----
    const unsigned digit0 = s.prefix >> 23;
    const unsigned ltmask = (lane == 31) ? 0x7fffffffu : ((1u << lane) - 1u);
#pragma unroll
    for (int i = 0; i < V4; i++) {
        const int i4 = i * TPB + tid;
        unsigned kk[4]; keys_of(xin[i4], kk);
#pragma unroll
        for (int j = 0; j < 4; j++) {
            const bool c = (kk[j] >> 23) == digit0;
            unsigned m = __ballot_sync(0xffffffffu, c);
            if (m) {
                const unsigned leader = __ffs(m) - 1u;
                int base = 0;
                if ((unsigned)lane == leader)
                    base = atomicAdd(&s.candCount, __popc(m));
                base = __shfl_sync(0xffffffffu, base, leader);
                if (c) {
                    int pos = base + __popc(m & ltmask);
                    if (pos < CAP)
                        s.u.cand[pos] =
                            ((unsigned long long)kk[j] << 32) | (unsigned)(i4 * 4 + j);
                }
            }
        }
    }
    __syncthreads();

    const int  cnt      = s.candCount;
    const bool overflow = (cnt > CAP);

    // ---- levels 1..3 refine over candidates (8+8+7 bits, no overlap) ----
#pragma unroll
    for (int lev = 1; lev < 4; lev++) {
        const int      shift = (lev == 1) ? 15 : (lev == 2) ? 7 : 0;
        const int      hi    = (lev == 1) ? 23 : (lev == 2) ? 15 : 7;
        const unsigned mask  = (lev == 3) ? 0x7fu : 0xffu;
        const unsigned pref_hi = s.prefix >> hi;

        if (tid < 256) s.tot[tid] = 0u;
        __syncthreads();

        if (!overflow) {
            const int cntPad = (cnt + TPB - 1) & ~(TPB - 1);
            for (int i = tid; i < cntPad; i += TPB) {
                unsigned d = 0x100u;
                if (i < cnt) {
                    unsigned key = (unsigned)(s.u.cand[i] >> 32);
                    if ((key >> hi) == pref_hi) d = (key >> shift) & mask;
                }
                hist_add_atomic(s.tot, d);
            }
        } else {  // rare fallback: re-scan the whole row from gmem/L2
#pragma unroll
            for (int i = 0; i < V4; i++) {
                unsigned kk[4]; keys_of(xin[i * TPB + tid], kk);
#pragma unroll
                for (int j = 0; j < 4; j++) {
                    unsigned d = ((kk[j] >> hi) == pref_hi) ? ((kk[j] >> shift) & mask)
                                                            : 0x100u;
                    hist_add_atomic(s.tot, d);
                }
            }
        }
        __syncthreads();
        if (tid < 32) select_bin(&s, shift);
        __syncthreads();
    }

    const unsigned thr = s.prefix;   // exact |x| bit pattern at the rank boundary
    // s.r = number of elements equal to thr still to keep (>=1)

    // ---- collect indices equal to threshold (lowest-index tie-break) ----
    if (!overflow) {
        for (int i = tid; i < cnt; i += TPB) {
            const unsigned long long rec = s.u.cand[i];
            if ((unsigned)(rec >> 32) == thr) {
                int pos = atomicAdd(&s.eqCount, 1);
                if (pos < EQ_CAP) s.eqIdx[pos] = (int)(unsigned)rec;
            }
        }
    } else {
#pragma unroll
        for (int i = 0; i < V4; i++) {
            const int i4 = i * TPB + tid;
            unsigned kk[4]; keys_of(xin[i4], kk);
#pragma unroll
            for (int j = 0; j < 4; j++) {
                if (kk[j] == thr) {
                    int pos = atomicAdd(&s.eqCount, 1);
                    if (pos < EQ_CAP) s.eqIdx[pos] = i4 * 4 + j;
                }
            }
        }
    }
    __syncthreads();
    if (tid == 0) {
        int e = s.eqCount; if (e > EQ_CAP) e = EQ_CAP;
        int m = s.r;       if (m > e) m = e;
        for (int a = 1; a < e; a++) {                 // tiny insertion sort
            int v = s.eqIdx[a]; int b = a - 1;
            while (b >= 0 && s.eqIdx[b] > v) { s.eqIdx[b + 1] = s.eqIdx[b]; b--; }
            s.eqIdx[b + 1] = v;
        }
        s.cutoff = (m > 0) ? s.eqIdx[m - 1] : -1;
    }
    __syncthreads();

    // ---- pass 3 (L2 re-read): masked output -> DRAM ----
    const int cut = s.cutoff;
#pragma unroll
    for (int i = 0; i < V4; i++) {
        const int i4 = i * TPB + tid;
        const float4 v = xin[i4];
        unsigned kk[4]; keys_of(v, kk);
        const int e0 = i4 * 4;
        float4 o;
        o.x = (kk[0] > thr || (kk[0] == thr && (e0 + 0) <= cut)) ? v.x : 0.f;
        o.y = (kk[1] > thr || (kk[1] == thr && (e0 + 1) <= cut)) ? v.y : 0.f;
        o.z = (kk[2] > thr || (kk[2] == thr && (e0 + 2) <= cut)) ? v.z : 0.f;
        o.w = (kk[3] > thr || (kk[3] == thr && (e0 + 3) <= cut)) ? v.w : 0.f;
        xout[i4] = o;
    }
}

extern "C" void kernel_launch(void* const* d_in, const int* in_sizes, int n_in,
                              void* d_out, int out_size)
{
    const float* x = (const float*)d_in[0];
    const int*   k = (const int*)d_in[1];
    float* out = (float*)d_out;
    const int rows = in_sizes[0] / COLS;

    topk_kernel<<<rows, TPB>>>(x, k, out);
}

// round 8
// speedup vs baseline: 1.2401x; 1.2401x over previous
#include <cuda_runtime.h>
#include <stdint.h>

#define COLS   16384
#define TPB    512
#define NW     (TPB / 32)
#define NCHUNK 4
#define CHUNK_F4   (COLS / 4 / NCHUNK)     // 1024 float4 per chunk
#define CHUNK_BYTES (COLS * 4 / NCHUNK)    // 16384 B
#define ITER_PER_CHUNK (CHUNK_F4 / TPB)    // 2 float4 per thread per chunk
#define CAP    2048
#define EQ_CAP 128

struct __align__(16) SmemT {
    unsigned long long mbar[NCHUNK];   // 32 B, 16B-aligned start keeps row aligned
    unsigned row[COLS];                // 64 KB : raw fp32 bits of the row
    union {
        unsigned           hist[NW][256];   // 16 KB (level 0 only)
        unsigned long long cand[CAP];       // 16 KB (key<<32)|idx
    } u;
    unsigned tot[256];
    int      eqIdx[EQ_CAP];
    unsigned prefix;
    int      r;
    int      eqCount;
    int      candCount;
    int      cutoff;
};

__device__ __forceinline__ unsigned smem_u32(const void* p) {
    return (unsigned)__cvta_generic_to_shared(p);
}

__device__ __forceinline__ void mbar_init(unsigned mbar, unsigned count) {
    asm volatile("mbarrier.init.shared.b64 [%0], %1;" :: "r"(mbar), "r"(count) : "memory");
}
__device__ __forceinline__ void mbar_expect_tx(unsigned mbar, unsigned bytes) {
    asm volatile("mbarrier.arrive.expect_tx.shared.b64 _, [%0], %1;"
                 :: "r"(mbar), "r"(bytes) : "memory");
}
__device__ __forceinline__ void bulk_g2s(unsigned dst_smem, const void* src, unsigned bytes,
                                         unsigned mbar) {
    asm volatile("cp.async.bulk.shared::cluster.global.mbarrier::complete_tx::bytes "
                 "[%0], [%1], %2, [%3];"
                 :: "r"(dst_smem), "l"(src), "r"(bytes), "r"(mbar) : "memory");
}
__device__ __forceinline__ void mbar_wait(unsigned mbar, unsigned parity) {
    unsigned done;
    asm volatile("{\n\t.reg .pred p;\n\t"
                 "mbarrier.try_wait.parity.acquire.cta.shared::cta.b64 p, [%1], %2;\n\t"
                 "selp.b32 %0, 1, 0, p;\n\t}"
                 : "=r"(done) : "r"(mbar), "r"(parity) : "memory");
    if (!done) {
        asm volatile("{\n\t.reg .pred P1;\n\t"
                     "W%=:\n\t"
                     "mbarrier.try_wait.parity.acquire.cta.shared::cta.b64 P1, [%0], %1, 0x989680;\n\t"
                     "@P1 bra.uni D%=;\n\t"
                     "bra.uni W%=;\n\t"
                     "D%=:\n\t}"
                     :: "r"(mbar), "r"(parity) : "memory");
    }
}

// Race-free per-warp histogram add (one warp owns h).
__device__ __forceinline__ void hist_add(unsigned* h, unsigned d) {
    unsigned mm = __match_any_sync(0xffffffffu, d);
    if (d < 256u) {
        unsigned leader = __ffs(mm) - 1u;
        if ((threadIdx.x & 31u) == leader) h[d] += (unsigned)__popc(mm);
    }
}
// Shared hist add with warp aggregation (multiple warps target h).
__device__ __forceinline__ void hist_add_atomic(unsigned* h, unsigned d) {
    unsigned mm = __match_any_sync(0xffffffffu, d);
    if (d < 256u) {
        unsigned leader = __ffs(mm) - 1u;
        if ((threadIdx.x & 31u) == leader) atomicAdd(&h[d], (unsigned)__popc(mm));
    }
}

// Warp 0: largest digit d with suffix_count(d) >= r; update prefix and r.
__device__ __forceinline__ void select_bin(SmemT* s, int shift) {
    const int lane = threadIdx.x & 31;
    const unsigned r = (unsigned)s->r;
    const unsigned base = (unsigned)lane * 8u;
    unsigned loc[8];
    unsigned sum = 0;
#pragma unroll
    for (int j = 7; j >= 0; j--) { sum += s->tot[base + j]; loc[j] = sum; }
    const unsigned lanesum = sum;
    unsigned acc = lanesum;
#pragma unroll
    for (int o = 1; o < 32; o <<= 1) {
        unsigned v = __shfl_down_sync(0xffffffffu, acc, o);
        if (lane < 32 - o) acc += v;
    }
    const unsigned above = acc - lanesum;
#pragma unroll
    for (int j = 0; j < 8; j++) {
        unsigned g     = above + loc[j];
        unsigned gnext = (j == 7) ? above : (above + loc[j+1]);
        if (g >= r && gnext < r) {
            s->prefix |= (base + (unsigned)j) << shift;
            s->r = (int)(r - gnext);
        }
    }
}

__device__ __forceinline__ void keys_of(float4 v, unsigned kk[4]) {
    kk[0] = __float_as_uint(v.x) & 0x7fffffffu;
    kk[1] = __float_as_uint(v.y) & 0x7fffffffu;
    kk[2] = __float_as_uint(v.z) & 0x7fffffffu;
    kk[3] = __float_as_uint(v.w) & 0x7fffffffu;
}

__global__ void __launch_bounds__(TPB, 2)
topk_kernel(const float* __restrict__ x, const int* __restrict__ kptr,
            float* __restrict__ out)
{
    extern __shared__ unsigned char smem_raw[];
    SmemT* s = reinterpret_cast<SmemT*>(smem_raw);
    const int tid  = threadIdx.x;
    const int w    = tid >> 5;
    const int lane = tid & 31;
    const size_t rowoff = (size_t)blockIdx.x * COLS;
    const float*  xrow = x + rowoff;
    const float4* xin  = reinterpret_cast<const float4*>(xrow);
    float4*       xout = reinterpret_cast<float4*>(out + rowoff);

    const int k = *kptr;
    if (k >= COLS) {
#pragma unroll
        for (int i = 0; i < COLS/4/TPB; i++) xout[i*TPB + tid] = xin[i*TPB + tid];
        return;
    }
    if (k <= 0) {
        float4 z = make_float4(0.f, 0.f, 0.f, 0.f);
#pragma unroll
        for (int i = 0; i < COLS/4/TPB; i++) xout[i*TPB + tid] = z;
        return;
    }

    // ---- init ----
    unsigned* hflat = &s->u.hist[0][0];
    for (int i = tid; i < NW * 256; i += TPB) hflat[i] = 0u;
    if (tid == 0) {
        s->prefix = 0u; s->r = k; s->eqCount = 0; s->candCount = 0;
#pragma unroll
        for (int c = 0; c < NCHUNK; c++) mbar_init(smem_u32(&s->mbar[c]), 1);
    }
    __syncthreads();

    // ---- kick off all bulk copies (gmem -> smem), chunked for early overlap ----
    if (tid == 0) {
#pragma unroll
        for (int c = 0; c < NCHUNK; c++) {
            unsigned mb = smem_u32(&s->mbar[c]);
            mbar_expect_tx(mb, CHUNK_BYTES);
            bulk_g2s(smem_u32(&s->row[0]) + c * CHUNK_BYTES,
                     xrow + c * (COLS / NCHUNK), CHUNK_BYTES, mb);
        }
    }

    // ---- pass 1: level-0 histogram from smem as chunks land ----
    unsigned* hw = s->u.hist[w];
    const float4* rowf4 = reinterpret_cast<const float4*>(s->row);
#pragma unroll
    for (int c = 0; c < NCHUNK; c++) {
        mbar_wait(smem_u32(&s->mbar[c]), 0u);
#pragma unroll
        for (int i = 0; i < ITER_PER_CHUNK; i++) {
            const int i4 = c * CHUNK_F4 + i * TPB + tid;
            unsigned kk[4]; keys_of(rowf4[i4], kk);
            hist_add(hw, kk[0] >> 23);
            hist_add(hw, kk[1] >> 23);
            hist_add(hw, kk[2] >> 23);
            hist_add(hw, kk[3] >> 23);
        }
    }
    __syncthreads();

    // ---- level 0: merge + select ----
    if (tid < 256) {
        unsigned t = 0;
#pragma unroll
        for (int ww = 0; ww < NW; ww++) t += s->u.hist[ww][tid];
        s->tot[tid] = t;
    }
    __syncthreads();
    if (tid < 32) select_bin(s, 23);
    __syncthreads();

    // ---- pass 2: compact candidates (smem read) ----
    const unsigned digit0 = s->prefix >> 23;
    const unsigned ltmask = (lane == 31) ? 0x7fffffffu : ((1u << lane) - 1u);
#pragma unroll
    for (int i = 0; i < COLS/4/TPB; i++) {
        const int i4 = i * TPB + tid;
        unsigned kk[4]; keys_of(rowf4[i4], kk);
#pragma unroll
        for (int j = 0; j < 4; j++) {
            const bool c = (kk[j] >> 23) == digit0;
            unsigned m = __ballot_sync(0xffffffffu, c);
            if (m) {
                const unsigned leader = __ffs(m) - 1u;
                int base = 0;
                if ((unsigned)lane == leader)
                    base = atomicAdd(&s->candCount, __popc(m));
                base = __shfl_sync(0xffffffffu, base, leader);
                if (c) {
                    int pos = base + __popc(m & ltmask);
                    if (pos < CAP)
                        s->u.cand[pos] =
                            ((unsigned long long)kk[j] << 32) | (unsigned)(i4 * 4 + j);
                }
            }
        }
    }
    __syncthreads();

    const int  cnt      = s->candCount;
    const bool overflow = (cnt > CAP);

    // ---- levels 1..3 refine (8+8+7 bits, non-overlapping) ----
#pragma unroll
    for (int lev = 1; lev < 4; lev++) {
        const int      shift = (lev == 1) ? 15 : (lev == 2) ? 7 : 0;
        const int      hi    = (lev == 1) ? 23 : (lev == 2) ? 15 : 7;
        const unsigned mask  = (lev == 3) ? 0x7fu : 0xffu;
        const unsigned pref_hi = s->prefix >> hi;

        if (tid < 256) s->tot[tid] = 0u;
        __syncthreads();

        if (!overflow) {
            const int cntPad = (cnt + TPB - 1) & ~(TPB - 1);
            for (int i = tid; i < cntPad; i += TPB) {
                unsigned d = 0x100u;
                if (i < cnt) {
                    unsigned key = (unsigned)(s->u.cand[i] >> 32);
                    if ((key >> hi) == pref_hi) d = (key >> shift) & mask;
                }
                hist_add_atomic(s->tot, d);
            }
        } else {
#pragma unroll
            for (int i = 0; i < COLS/4/TPB; i++) {
                unsigned kk[4]; keys_of(rowf4[i * TPB + tid], kk);
#pragma unroll
                for (int j = 0; j < 4; j++) {
                    unsigned d = ((kk[j] >> hi) == pref_hi) ? ((kk[j] >> shift) & mask)
                                                            : 0x100u;
                    hist_add_atomic(s->tot, d);
                }
            }
        }
        __syncthreads();
        if (tid < 32) select_bin(s, shift);
        __syncthreads();
    }

    const unsigned thr = s->prefix;

    // ---- tie-break: collect indices equal to threshold ----
    if (!overflow) {
        for (int i = tid; i < cnt; i += TPB) {
            const unsigned long long rec = s->u.cand[i];
            if ((unsigned)(rec >> 32) == thr) {
                int pos = atomicAdd(&s->eqCount, 1);
                if (pos < EQ_CAP) s->eqIdx[pos] = (int)(unsigned)rec;
            }
        }
    } else {
#pragma unroll
        for (int i = 0; i < COLS/4/TPB; i++) {
            const int i4 = i * TPB + tid;
            unsigned kk[4]; keys_of(rowf4[i4], kk);
#pragma unroll
            for (int j = 0; j < 4; j++) {
                if (kk[j] == thr) {
                    int pos = atomicAdd(&s->eqCount, 1);
                    if (pos < EQ_CAP) s->eqIdx[pos] = i4 * 4 + j;
                }
            }
        }
    }
    __syncthreads();
    if (tid == 0) {
        int e = s->eqCount; if (e > EQ_CAP) e = EQ_CAP;
        int m = s->r;       if (m > e) m = e;
        for (int a = 1; a < e; a++) {
            int v = s->eqIdx[a]; int b = a - 1;
            while (b >= 0 && s->eqIdx[b] > v) { s->eqIdx[b + 1] = s->eqIdx[b]; b--; }
            s->eqIdx[b + 1] = v;
        }
        s->cutoff = (m > 0) ? s->eqIdx[m - 1] : -1;
    }
    __syncthreads();

    // ---- output: smem -> gmem, streaming stores (no L2 pollution) ----
    const int cut = s->cutoff;
#pragma unroll
    for (int i = 0; i < COLS/4/TPB; i++) {
        const int i4 = i * TPB + tid;
        const float4 v = rowf4[i4];
        unsigned kk[4]; keys_of(v, kk);
        const int e0 = i4 * 4;
        float4 o;
        o.x = (kk[0] > thr || (kk[0] == thr && (e0 + 0) <= cut)) ? v.x : 0.f;
        o.y = (kk[1] > thr || (kk[1] == thr && (e0 + 1) <= cut)) ? v.y : 0.f;
        o.z = (kk[2] > thr || (kk[2] == thr && (e0 + 2) <= cut)) ? v.z : 0.f;
        o.w = (kk[3] > thr || (kk[3] == thr && (e0 + 3) <= cut)) ? v.w : 0.f;
        __stcs(&xout[i4], o);
    }
}

extern "C" void kernel_launch(void* const* d_in, const int* in_sizes, int n_in,
                              void* d_out, int out_size)
{
    const float* x = (const float*)d_in[0];
    const int*   k = (const int*)d_in[1];
    float* out = (float*)d_out;
    const int rows = in_sizes[0] / COLS;

    cudaFuncSetAttribute(topk_kernel,
                         cudaFuncAttributeMaxDynamicSharedMemorySize,
                         (int)sizeof(SmemT));
    topk_kernel<<<rows, TPB, sizeof(SmemT)>>>(x, k, out);
}